// round 9
// baseline (speedup 1.0000x reference)
#include <cuda_runtime.h>
#include <cuda_fp16.h>
#include <stdint.h>

// Fused LIF step, sm_103-portable (mma.sync HMMA).
// i_in*64 = x0@W0 + x1@W0 + x0@W1 + z@R0 + z@R1, fp32 accum (error ~5e-8).
// Weights pre-split into ks-major fragment-ordered fp16 tiles in gmem
// (L2-resident). Per-warp private 3-slot cp.async ring streams the warp's
// 1KB N-quarter per stage; NO __syncthreads in the MMA loop.
// R9: stages ordered tile-inner/ks-outer so A fragments (x0, z) are reused
// across adjacent stages (ldsm4 per ks: 10 -> 6), and the LIF epilogue runs
// directly from accumulator registers (no i_in smem staging round-trip).
// smem = X0+X1+Z (48KB) + ring (24KB) = 72KB -> 3 CTAs/SM.

typedef unsigned long long u64;
typedef uint32_t u32;

#define TBX 256
#define WSCALE 64.0f
#define INV_WSCALE 0.015625f

#define T_X0   0u
#define T_X1   16384u
#define T_Z    32768u
#define T_RING 49152u
#define SMEM_BYTES 73728

// 4 split-weight tiles [W0,W1,R0,R1], ks-major fragment order:
// frag f = (ks*16 + nb)*32 + lane ; u64 = {b0:half2, b1:half2}.
// One ks-stage of one tile = 512 u64 = 4KB; one N-quarter = 1KB.
__device__ __align__(16) u64 g_wfrag[4][4096];

static __device__ __forceinline__ u32 s2u(const void* p){
  u32 a; asm("{ .reg .u64 t; cvta.to.shared.u64 t, %1; cvt.u32.u64 %0, t; }":"=r"(a):"l"(p)); return a;
}
static __device__ __forceinline__ u32 swz16(int r, int c){   // fp16 tile, 256B rows
  return (u32)((r<<8) + ((((c>>3) ^ (r&7)) & 15)<<4) + ((c&7)<<1));
}
static __device__ __forceinline__ void sts64(u32 a, u32 lo, u32 hi){
  asm volatile("st.shared.v2.u32 [%0], {%1,%2};"::"r"(a),"r"(lo),"r"(hi));
}
static __device__ __forceinline__ u32 h2u(__half2 h){ return *reinterpret_cast<u32*>(&h); }

static __device__ __forceinline__ void split_store4(u32 a0, u32 a1, float4 f){
  __half h00=__float2half_rn(f.x), h01=__float2half_rn(f.y);
  __half h02=__float2half_rn(f.z), h03=__float2half_rn(f.w);
  sts64(a0, h2u(__halves2half2(h00,h01)), h2u(__halves2half2(h02,h03)));
  __half h10=__float2half_rn(f.x-__half2float(h00));
  __half h11=__float2half_rn(f.y-__half2float(h01));
  __half h12=__float2half_rn(f.z-__half2float(h02));
  __half h13=__float2half_rn(f.w-__half2float(h03));
  sts64(a1, h2u(__halves2half2(h10,h11)), h2u(__halves2half2(h12,h13)));
}
static __device__ __forceinline__ void ldsm4(u32 addr, u32* r){
  asm volatile("ldmatrix.sync.aligned.m8n8.x4.shared.b16 {%0,%1,%2,%3}, [%4];"
               : "=r"(r[0]),"=r"(r[1]),"=r"(r[2]),"=r"(r[3]) : "r"(addr));
}
static __device__ __forceinline__ void mma16816(float* c, const u32* a, u32 b0, u32 b1){
  asm volatile("mma.sync.aligned.m16n8k16.row.col.f32.f16.f16.f32 "
               "{%0,%1,%2,%3}, {%4,%5,%6,%7}, {%8,%9}, {%0,%1,%2,%3};"
               : "+f"(c[0]),"+f"(c[1]),"+f"(c[2]),"+f"(c[3])
               : "r"(a[0]),"r"(a[1]),"r"(a[2]),"r"(a[3]), "r"(b0),"r"(b1));
}
static __device__ __forceinline__ void cpasync16(u32 dst, const void* src){
  asm volatile("cp.async.cg.shared.global [%0], [%1], 16;" :: "r"(dst), "l"(src));
}

// ---- prep: split w*64 into ks-major fragment-ordered fp16 tiles (once/launch)
__global__ void prep_wfrag(const float* __restrict__ win,
                           const float* __restrict__ wrec)
{
  int idx = blockIdx.x * blockDim.x + threadIdx.x;   // 0..8191
  int mat = idx >> 12;        // 0=w_in, 1=w_rec
  int f   = idx & 4095;
  int ks   = f >> 9;          // kstep 0..7
  int nb   = (f >> 5) & 15;   // n8 block 0..15
  int lane = f & 31;
  int n  = nb*8 + (lane >> 2);
  int kb = ks*16 + (lane & 3)*2;
  const float* W = mat ? wrec : win;
  float w[4] = { W[kb*128 + n]     * WSCALE, W[(kb+1)*128 + n] * WSCALE,
                 W[(kb+8)*128 + n] * WSCALE, W[(kb+9)*128 + n] * WSCALE };
  __half p[4], r[4];
#pragma unroll
  for (int i = 0; i < 4; i++) {
    p[i] = __float2half_rn(w[i]);
    r[i] = __float2half_rn(w[i] - __half2float(p[i]));
  }
  u64 prim = ((u64)h2u(__halves2half2(p[2],p[3])) << 32) | h2u(__halves2half2(p[0],p[1]));
  u64 resi = ((u64)h2u(__halves2half2(r[2],r[3])) << 32) | h2u(__halves2half2(r[0],r[1]));
  g_wfrag[mat*2 + 0][f] = prim;
  g_wfrag[mat*2 + 1][f] = resi;
}

__global__ __launch_bounds__(TBX, 3)
void lif_hmma_kernel(const float* __restrict__ gx, const float* __restrict__ gz,
                     const float* __restrict__ gv, const float* __restrict__ gt,
                     float* __restrict__ out, int Btot, long long out_elems)
{
  extern __shared__ __align__(1024) char smem[];
  const u32 sb = s2u(smem);
  const int tid = threadIdx.x;
  const int wid = tid >> 5, lid = tid & 31;
  const u32 browg = (u32)blockIdx.x * 64;      // 64-row tile

  const int wr = wid & 1;                  // row group (32 rows)
  const int wc = wid >> 1;                 // col quarter (32 cols, 4 n8 blocks)
  const int mrow = wr << 5;
  const u32 ring = sb + T_RING + (u32)wid*3072;   // private 3x1KB slots

  // stage s (0..31): ks = s>>2, B tile bt = s&3 (W0,W1,R0,R1).
  auto issue_stage = [&](int s, int slot){
    if (s < 32) {
      const char* src = reinterpret_cast<const char*>(g_wfrag[s & 3])
                      + (s >> 2)*4096 + wc*1024 + lid*32;
      u32 dst = ring + (u32)(slot*1024 + lid*32);
      cpasync16(dst, src);
      cpasync16(dst + 16u, src + 16);
    }
    asm volatile("cp.async.commit_group;" ::: "memory");
  };

  issue_stage(0, 0); issue_stage(1, 1); issue_stage(2, 2);

  // ===== producer: x split + z pack into smem (64x128) =====
  {
    const float4* X4 = reinterpret_cast<const float4*>(gx) + (size_t)browg*32;
    const float4* Z4 = reinterpret_cast<const float4*>(gz) + (size_t)browg*32;
#pragma unroll
    for (int q = 0; q < 8; q++) {
      int e = q*TBX + tid;                 // 2048 float4 = 64x128
      int r = e >> 5, c4 = (e & 31) << 2;
      u32 so = swz16(r, c4);
      split_store4(sb + T_X0 + so, sb + T_X1 + so, X4[e]);
      float4 zv = Z4[e];
      sts64(sb + T_Z + so,
            h2u(__floats2half2_rn(zv.x, zv.y)),
            h2u(__floats2half2_rn(zv.z, zv.w)));
    }
  }
  __syncthreads();      // X/Z ready; the only barrier in the kernel

  // ===== MMA mainloop: barrier-free; A fragments reused across stages =====
  const int a_r  = (lid & 7) + ((lid >> 3) & 1) * 8;
  const int a_k8 = (lid >> 4) * 8;

  float acc[2][4][4];
#pragma unroll
  for (int mt = 0; mt < 2; mt++)
#pragma unroll
    for (int j = 0; j < 4; j++)
#pragma unroll
      for (int k = 0; k < 4; k++) acc[mt][j][k] = 0.0f;

  int slot = 0;
#pragma unroll 1
  for (int ks = 0; ks < 8; ks++) {
    const int kb = ks << 4;
    const int s0 = ks << 2;
    u32 ax0[2][4], ax1[2][4], az[2][4];
    uint2 b[4];

    auto read_b = [&](){
      asm volatile("cp.async.wait_group 2;" ::: "memory");
      const u32 rbase = ring + (u32)(slot*1024 + lid*8);
#pragma unroll
      for (int j = 0; j < 4; j++)
        asm volatile("ld.shared.v2.u32 {%0,%1}, [%2];"
                     : "=r"(b[j].x), "=r"(b[j].y) : "r"(rbase + (u32)(j*256)));
    };
    auto next = [&](int s){ issue_stage(s + 3, slot); slot = (slot == 2) ? 0 : slot + 1; };

    // bt=0 : W0 with x0 and x1
    read_b();
#pragma unroll
    for (int mt = 0; mt < 2; mt++) {
      ldsm4(sb + T_X0 + swz16(mrow + mt*16 + a_r, kb + a_k8), ax0[mt]);
      ldsm4(sb + T_X1 + swz16(mrow + mt*16 + a_r, kb + a_k8), ax1[mt]);
    }
#pragma unroll
    for (int mt = 0; mt < 2; mt++)
#pragma unroll
      for (int j = 0; j < 4; j++) {
        mma16816(acc[mt][j], ax0[mt], b[j].x, b[j].y);
        mma16816(acc[mt][j], ax1[mt], b[j].x, b[j].y);
      }
    next(s0);

    // bt=1 : W1 with x0 (reused)
    read_b();
#pragma unroll
    for (int mt = 0; mt < 2; mt++)
#pragma unroll
      for (int j = 0; j < 4; j++)
        mma16816(acc[mt][j], ax0[mt], b[j].x, b[j].y);
    next(s0 + 1);

    // bt=2 : R0 with z
    read_b();
#pragma unroll
    for (int mt = 0; mt < 2; mt++)
      ldsm4(sb + T_Z + swz16(mrow + mt*16 + a_r, kb + a_k8), az[mt]);
#pragma unroll
    for (int mt = 0; mt < 2; mt++)
#pragma unroll
      for (int j = 0; j < 4; j++)
        mma16816(acc[mt][j], az[mt], b[j].x, b[j].y);
    next(s0 + 2);

    // bt=3 : R1 with z (reused)
    read_b();
#pragma unroll
    for (int mt = 0; mt < 2; mt++)
#pragma unroll
      for (int j = 0; j < 4; j++)
        mma16816(acc[mt][j], az[mt], b[j].x, b[j].y);
    next(s0 + 3);
  }

  // ===== LIF epilogue straight from accumulators (no smem staging) =====
  const float L2D = -0.07400058144377693f;   // log2(0.95)
  const u32 NB = (u32)Btot * 128u;
  const bool has_t = (out_elems >= (long long)NB * 3);
  const int rq = lid >> 2, cq = (lid & 3) << 1;
  const int ncol = wc << 5;

#pragma unroll
  for (int mt = 0; mt < 2; mt++)
#pragma unroll
    for (int half = 0; half < 2; half++) {
      const int row = mrow + mt*16 + half*8 + rq;
#pragma unroll
      for (int j = 0; j < 4; j++) {
        const int c = ncol + j*8 + cq;
        float i0 = acc[mt][j][half*2 + 0] * INV_WSCALE;
        float i1 = acc[mt][j][half*2 + 1] * INV_WSCALE;

        // z (exact fp16) from resident smem tile: packed pair at (row, c)
        u32 zp;
        asm volatile("ld.shared.b32 %0, [%1];" : "=r"(zp)
                     : "r"(sb + T_Z + swz16(row, c)));
        __half2 zh = *reinterpret_cast<__half2*>(&zp);
        float z0 = __half2float(__low2half(zh));
        float z1 = __half2float(__high2half(zh));

        const u32 gi = (browg + (u32)row)*128u + (u32)c;
        float2 vv = *reinterpret_cast<const float2*>(gv + gi);
        float2 tv = *reinterpret_cast<const float2*>(gt + gi);

        float iin[2] = {i0, i1};
        float zf[2]  = {z0, z1};
        float va[2]  = {vv.x, vv.y};
        float ta[2]  = {tv.x, tv.y};
        float nz[2], nv2[2], nt2[2];
#pragma unroll
        for (int e = 0; e < 2; e++) {
          float h  = (iin[e] != 0.0f) ? 1.0f : 0.0f;
          float nt = ta[e] + (1.0f - h);
          float nv = va[e] * (1.0f - zf[e]);
          if (!(va[e] > -1.0f)) nv -= (va[e] + 1.0f);
          nv *= exp2f(h * (nt + 1.0f) * L2D);
          nt *= (1.0f - h);
          nv += iin[e];
          nz[e]  = (nv > 0.4f) ? 1.0f : 0.0f;
          nv2[e] = nv; nt2[e] = nt;
        }
        *reinterpret_cast<float2*>(out + gi)      = make_float2(nz[0],  nz[1]);
        *reinterpret_cast<float2*>(out + NB + gi) = make_float2(nv2[0], nv2[1]);
        if (has_t)
          *reinterpret_cast<float2*>(out + 2u*NB + gi) = make_float2(nt2[0], nt2[1]);
      }
    }
}

extern "C" void kernel_launch(void* const* d_in, const int* in_sizes, int n_in,
                              void* d_out, int out_size)
{
  const float* x     = (const float*)d_in[0];
  const float* z     = (const float*)d_in[1];
  const float* v     = (const float*)d_in[2];
  const float* t     = (const float*)d_in[3];
  const float* w_in  = (const float*)d_in[4];
  const float* w_rec = (const float*)d_in[5];

  const int B = in_sizes[0] / 128;       // 131072
  const int grid = B / 64;               // 2048 CTAs

  cudaFuncSetAttribute(lif_hmma_kernel,
                       cudaFuncAttributeMaxDynamicSharedMemorySize, SMEM_BYTES);

  prep_wfrag<<<32, 256>>>(w_in, w_rec);
  lif_hmma_kernel<<<grid, TBX, SMEM_BYTES>>>(x, z, v, t,
                                             (float*)d_out, B, (long long)out_size);
}

// round 10
// speedup vs baseline: 1.1443x; 1.1443x over previous
#include <cuda_runtime.h>
#include <cuda_fp16.h>
#include <stdint.h>

// Fused LIF step, sm_103-portable (mma.sync HMMA).
// i_in*64 = x0@W0 + x1@W0 + x0@W1 + z@R0 + z@R1, fp32 accum (error ~5e-8).
// Weights pre-split into ks-major fragment-ordered fp16 tiles in gmem
// (L2-resident). Per-warp private 3-slot cp.async ring streams the warp's
// 1KB N-quarter per stage; NO __syncthreads in the MMA loop.
// R10 = R8 staging/epilogue (coalesced float4 gmem I/O via smem i_in staging)
//     + R9 mainloop (tile-inner/ks-outer stages, A fragments x0/z reused
//       across adjacent stages: ldsm4 per ks 10 -> 6).
// smem = X0+X1+Z (48KB) + ring (24KB) = 72KB -> 3 CTAs/SM.

typedef unsigned long long u64;
typedef uint32_t u32;

#define TBX 256
#define WSCALE 64.0f
#define INV_WSCALE 0.015625f

#define T_X0   0u
#define T_X1   16384u
#define T_Z    32768u
#define T_RING 49152u
#define SMEM_BYTES 73728
// fp32 i_in staging (32KB) aliases X0+X1 after MMA.

// 4 split-weight tiles [W0,W1,R0,R1], ks-major fragment order:
// frag f = (ks*16 + nb)*32 + lane ; u64 = {b0:half2, b1:half2}.
// One ks-stage of one tile = 512 u64 = 4KB; one N-quarter = 1KB.
__device__ __align__(16) u64 g_wfrag[4][4096];

static __device__ __forceinline__ u32 s2u(const void* p){
  u32 a; asm("{ .reg .u64 t; cvta.to.shared.u64 t, %1; cvt.u32.u64 %0, t; }":"=r"(a):"l"(p)); return a;
}
static __device__ __forceinline__ u32 swz16(int r, int c){   // fp16 tile, 256B rows
  return (u32)((r<<8) + ((((c>>3) ^ (r&7)) & 15)<<4) + ((c&7)<<1));
}
static __device__ __forceinline__ u32 swz32(int r, int c){   // fp32 staging, 512B rows
  return (u32)((r<<9) + ((((c>>2) ^ (r&7)) & 31)<<4) + ((c&3)<<2));
}
static __device__ __forceinline__ void sts64(u32 a, u32 lo, u32 hi){
  asm volatile("st.shared.v2.u32 [%0], {%1,%2};"::"r"(a),"r"(lo),"r"(hi));
}
static __device__ __forceinline__ void stsf2(u32 a, float x, float y){
  asm volatile("st.shared.v2.f32 [%0], {%1,%2};"::"r"(a),"f"(x),"f"(y));
}
static __device__ __forceinline__ u32 h2u(__half2 h){ return *reinterpret_cast<u32*>(&h); }

static __device__ __forceinline__ void split_store4(u32 a0, u32 a1, float4 f){
  __half h00=__float2half_rn(f.x), h01=__float2half_rn(f.y);
  __half h02=__float2half_rn(f.z), h03=__float2half_rn(f.w);
  sts64(a0, h2u(__halves2half2(h00,h01)), h2u(__halves2half2(h02,h03)));
  __half h10=__float2half_rn(f.x-__half2float(h00));
  __half h11=__float2half_rn(f.y-__half2float(h01));
  __half h12=__float2half_rn(f.z-__half2float(h02));
  __half h13=__float2half_rn(f.w-__half2float(h03));
  sts64(a1, h2u(__halves2half2(h10,h11)), h2u(__halves2half2(h12,h13)));
}
static __device__ __forceinline__ void ldsm4(u32 addr, u32* r){
  asm volatile("ldmatrix.sync.aligned.m8n8.x4.shared.b16 {%0,%1,%2,%3}, [%4];"
               : "=r"(r[0]),"=r"(r[1]),"=r"(r[2]),"=r"(r[3]) : "r"(addr));
}
static __device__ __forceinline__ void mma16816(float* c, const u32* a, u32 b0, u32 b1){
  asm volatile("mma.sync.aligned.m16n8k16.row.col.f32.f16.f16.f32 "
               "{%0,%1,%2,%3}, {%4,%5,%6,%7}, {%8,%9}, {%0,%1,%2,%3};"
               : "+f"(c[0]),"+f"(c[1]),"+f"(c[2]),"+f"(c[3])
               : "r"(a[0]),"r"(a[1]),"r"(a[2]),"r"(a[3]), "r"(b0),"r"(b1));
}
static __device__ __forceinline__ void cpasync16(u32 dst, const void* src){
  asm volatile("cp.async.cg.shared.global [%0], [%1], 16;" :: "r"(dst), "l"(src));
}

// ---- prep: split w*64 into ks-major fragment-ordered fp16 tiles (once/launch)
__global__ void prep_wfrag(const float* __restrict__ win,
                           const float* __restrict__ wrec)
{
  int idx = blockIdx.x * blockDim.x + threadIdx.x;   // 0..8191
  int mat = idx >> 12;        // 0=w_in, 1=w_rec
  int f   = idx & 4095;
  int ks   = f >> 9;          // kstep 0..7
  int nb   = (f >> 5) & 15;   // n8 block 0..15
  int lane = f & 31;
  int n  = nb*8 + (lane >> 2);
  int kb = ks*16 + (lane & 3)*2;
  const float* W = mat ? wrec : win;
  float w[4] = { W[kb*128 + n]     * WSCALE, W[(kb+1)*128 + n] * WSCALE,
                 W[(kb+8)*128 + n] * WSCALE, W[(kb+9)*128 + n] * WSCALE };
  __half p[4], r[4];
#pragma unroll
  for (int i = 0; i < 4; i++) {
    p[i] = __float2half_rn(w[i]);
    r[i] = __float2half_rn(w[i] - __half2float(p[i]));
  }
  u64 prim = ((u64)h2u(__halves2half2(p[2],p[3])) << 32) | h2u(__halves2half2(p[0],p[1]));
  u64 resi = ((u64)h2u(__halves2half2(r[2],r[3])) << 32) | h2u(__halves2half2(r[0],r[1]));
  g_wfrag[mat*2 + 0][f] = prim;
  g_wfrag[mat*2 + 1][f] = resi;
}

__global__ __launch_bounds__(TBX, 3)
void lif_hmma_kernel(const float* __restrict__ gx, const float* __restrict__ gz,
                     const float* __restrict__ gv, const float* __restrict__ gt,
                     float* __restrict__ out, int Btot, long long out_elems)
{
  extern __shared__ __align__(1024) char smem[];
  const u32 sb = s2u(smem);
  const int tid = threadIdx.x;
  const int wid = tid >> 5, lid = tid & 31;
  const u32 browg = (u32)blockIdx.x * 64;      // 64-row tile

  const int wr = wid & 1;                  // row group (32 rows)
  const int wc = wid >> 1;                 // col quarter (32 cols, 4 n8 blocks)
  const int mrow = wr << 5;
  const u32 ring = sb + T_RING + (u32)wid*3072;   // private 3x1KB slots

  // stage s (0..31): ks = s>>2, B tile bt = s&3 (W0,W1,R0,R1).
  auto issue_stage = [&](int s, int slot){
    if (s < 32) {
      const char* src = reinterpret_cast<const char*>(g_wfrag[s & 3])
                      + (s >> 2)*4096 + wc*1024 + lid*32;
      u32 dst = ring + (u32)(slot*1024 + lid*32);
      cpasync16(dst, src);
      cpasync16(dst + 16u, src + 16);
    }
    asm volatile("cp.async.commit_group;" ::: "memory");
  };

  issue_stage(0, 0); issue_stage(1, 1); issue_stage(2, 2);

  // ===== producer: x split + z pack into smem (64x128) =====
  {
    const float4* X4 = reinterpret_cast<const float4*>(gx) + (size_t)browg*32;
    const float4* Z4 = reinterpret_cast<const float4*>(gz) + (size_t)browg*32;
#pragma unroll
    for (int q = 0; q < 8; q++) {
      int e = q*TBX + tid;                 // 2048 float4 = 64x128
      int r = e >> 5, c4 = (e & 31) << 2;
      u32 so = swz16(r, c4);
      split_store4(sb + T_X0 + so, sb + T_X1 + so, X4[e]);
      float4 zv = Z4[e];
      sts64(sb + T_Z + so,
            h2u(__floats2half2_rn(zv.x, zv.y)),
            h2u(__floats2half2_rn(zv.z, zv.w)));
    }
  }
  __syncthreads();      // X/Z ready

  // ===== MMA mainloop: barrier-free; A fragments reused across stages =====
  const int a_r  = (lid & 7) + ((lid >> 3) & 1) * 8;
  const int a_k8 = (lid >> 4) * 8;

  float acc[2][4][4];
#pragma unroll
  for (int mt = 0; mt < 2; mt++)
#pragma unroll
    for (int j = 0; j < 4; j++)
#pragma unroll
      for (int k = 0; k < 4; k++) acc[mt][j][k] = 0.0f;

  int slot = 0;
#pragma unroll 1
  for (int ks = 0; ks < 8; ks++) {
    const int kb = ks << 4;
    const int s0 = ks << 2;
    u32 ax0[2][4], ax1[2][4], az[2][4];
    uint2 b[4];

    auto read_b = [&](){
      asm volatile("cp.async.wait_group 2;" ::: "memory");
      const u32 rbase = ring + (u32)(slot*1024 + lid*8);
#pragma unroll
      for (int j = 0; j < 4; j++)
        asm volatile("ld.shared.v2.u32 {%0,%1}, [%2];"
                     : "=r"(b[j].x), "=r"(b[j].y) : "r"(rbase + (u32)(j*256)));
    };
    auto next = [&](int s){ issue_stage(s + 3, slot); slot = (slot == 2) ? 0 : slot + 1; };

    // bt=0 : W0 with x0 and x1
    read_b();
#pragma unroll
    for (int mt = 0; mt < 2; mt++) {
      ldsm4(sb + T_X0 + swz16(mrow + mt*16 + a_r, kb + a_k8), ax0[mt]);
      ldsm4(sb + T_X1 + swz16(mrow + mt*16 + a_r, kb + a_k8), ax1[mt]);
    }
#pragma unroll
    for (int mt = 0; mt < 2; mt++)
#pragma unroll
      for (int j = 0; j < 4; j++) {
        mma16816(acc[mt][j], ax0[mt], b[j].x, b[j].y);
        mma16816(acc[mt][j], ax1[mt], b[j].x, b[j].y);
      }
    next(s0);

    // bt=1 : W1 with x0 (reused)
    read_b();
#pragma unroll
    for (int mt = 0; mt < 2; mt++)
#pragma unroll
      for (int j = 0; j < 4; j++)
        mma16816(acc[mt][j], ax0[mt], b[j].x, b[j].y);
    next(s0 + 1);

    // bt=2 : R0 with z
    read_b();
#pragma unroll
    for (int mt = 0; mt < 2; mt++)
      ldsm4(sb + T_Z + swz16(mrow + mt*16 + a_r, kb + a_k8), az[mt]);
#pragma unroll
    for (int mt = 0; mt < 2; mt++)
#pragma unroll
      for (int j = 0; j < 4; j++)
        mma16816(acc[mt][j], az[mt], b[j].x, b[j].y);
    next(s0 + 2);

    // bt=3 : R1 with z (reused)
    read_b();
#pragma unroll
    for (int mt = 0; mt < 2; mt++)
#pragma unroll
      for (int j = 0; j < 4; j++)
        mma16816(acc[mt][j], az[mt], b[j].x, b[j].y);
    next(s0 + 3);
  }

  __syncthreads();   // all X0/X1 ldmatrix reads done before staging overwrites

  // ===== acc -> fp32 i_in staging (aliases X0/X1), scaled by 1/64 =====
  {
    const int rq = lid >> 2, cq = (lid & 3) << 1;
    const int ncol = wc << 5;
#pragma unroll
    for (int mt = 0; mt < 2; mt++) {
      const int r0 = mrow + mt*16 + rq;
#pragma unroll
      for (int j = 0; j < 4; j++) {
        const int c = ncol + j*8 + cq;
        stsf2(sb + swz32(r0,     c), acc[mt][j][0]*INV_WSCALE, acc[mt][j][1]*INV_WSCALE);
        stsf2(sb + swz32(r0 + 8, c), acc[mt][j][2]*INV_WSCALE, acc[mt][j][3]*INV_WSCALE);
      }
    }
  }
  __syncthreads();

  // ===== coalesced fused LIF epilogue =====
  const float L2D = -0.07400058144377693f;   // log2(0.95)
  const u32 NB = (u32)Btot * 128u;
  const bool has_t = (out_elems >= (long long)NB * 3);
#pragma unroll
  for (int q = 0; q < 8; q++) {
    int e4  = ((q << 8) + tid) << 2;         // 0..8188
    int row = e4 >> 7, col = e4 & 127;
    float4 iv;
    asm volatile("ld.shared.v4.f32 {%0,%1,%2,%3}, [%4];"
                 : "=f"(iv.x),"=f"(iv.y),"=f"(iv.z),"=f"(iv.w)
                 : "r"(sb + swz32(row, col)));
    u32 zl, zh;
    asm volatile("ld.shared.v2.u32 {%0,%1}, [%2];" : "=r"(zl),"=r"(zh)
                 : "r"(sb + T_Z + swz16(row, col)));
    __half2 zp0 = *reinterpret_cast<__half2*>(&zl);
    __half2 zp1 = *reinterpret_cast<__half2*>(&zh);
    float zf[4] = {__half2float(__low2half(zp0)), __half2float(__high2half(zp0)),
                   __half2float(__low2half(zp1)), __half2float(__high2half(zp1))};
    u32 gi = browg*128u + (u32)e4;
    float4 vv = reinterpret_cast<const float4*>(gv)[gi>>2];
    float4 tv = reinterpret_cast<const float4*>(gt)[gi>>2];
    float ia[4] = {iv.x, iv.y, iv.z, iv.w};
    float va[4] = {vv.x, vv.y, vv.z, vv.w};
    float ta[4] = {tv.x, tv.y, tv.z, tv.w};
    float nzo[4], nvo[4], nto[4];
#pragma unroll
    for (int j = 0; j < 4; j++) {
      float iin = ia[j];
      float h  = (iin != 0.0f) ? 1.0f : 0.0f;
      float nt = ta[j] + (1.0f - h);
      float nv = va[j] * (1.0f - zf[j]);
      if (!(va[j] > -1.0f)) nv -= (va[j] + 1.0f);
      nv *= exp2f(h * (nt + 1.0f) * L2D);
      nt *= (1.0f - h);
      nv += iin;
      nzo[j] = (nv > 0.4f) ? 1.0f : 0.0f;
      nvo[j] = nv; nto[j] = nt;
    }
    float4 o;
    o.x=nzo[0]; o.y=nzo[1]; o.z=nzo[2]; o.w=nzo[3];
    *reinterpret_cast<float4*>(&out[gi]) = o;
    o.x=nvo[0]; o.y=nvo[1]; o.z=nvo[2]; o.w=nvo[3];
    *reinterpret_cast<float4*>(&out[NB + gi]) = o;
    if (has_t) {
      o.x=nto[0]; o.y=nto[1]; o.z=nto[2]; o.w=nto[3];
      *reinterpret_cast<float4*>(&out[2u*NB + gi]) = o;
    }
  }
}

extern "C" void kernel_launch(void* const* d_in, const int* in_sizes, int n_in,
                              void* d_out, int out_size)
{
  const float* x     = (const float*)d_in[0];
  const float* z     = (const float*)d_in[1];
  const float* v     = (const float*)d_in[2];
  const float* t     = (const float*)d_in[3];
  const float* w_in  = (const float*)d_in[4];
  const float* w_rec = (const float*)d_in[5];

  const int B = in_sizes[0] / 128;       // 131072
  const int grid = B / 64;               // 2048 CTAs

  cudaFuncSetAttribute(lif_hmma_kernel,
                       cudaFuncAttributeMaxDynamicSharedMemorySize, SMEM_BYTES);

  prep_wfrag<<<32, 256>>>(w_in, w_rec);
  lif_hmma_kernel<<<grid, TBX, SMEM_BYTES>>>(x, z, v, t,
                                             (float*)d_out, B, (long long)out_size);
}

// round 11
// speedup vs baseline: 1.3269x; 1.1595x over previous
#include <cuda_runtime.h>
#include <cuda_fp16.h>
#include <stdint.h>

// Fused LIF step, sm_103-portable (mma.sync HMMA).
// i_in*64 = x0@W0 + x1@W0 + x0@W1 + z@R0 + z@R1, fp32 accum (error ~5e-8).
// Weights pre-split into ks-major fragment-ordered fp16 tiles in gmem
// (L2-resident, shared by all CTAs).
// R11: CTA-shared lockstep 4-deep cp.async ring (4KB/stage, each thread 16B)
//      -> ring smem-write traffic halved vs R8/R10's duplicated private rings.
//      Per-stage __syncthreads (proven ~free in R7).
// Mainloop: tile-inner/ks-outer stages, A fragments (x0, z) reused across
// adjacent stages (ldsm4 per ks: 6). Coalesced float4 epilogue via smem
// i_in staging (aliases X0/X1).
// smem = X0+X1+Z (48KB) + ring (16KB) = 64KB -> 3 CTAs/SM.

typedef unsigned long long u64;
typedef uint32_t u32;

#define TBX 256
#define WSCALE 64.0f
#define INV_WSCALE 0.015625f

#define T_X0   0u
#define T_X1   16384u
#define T_Z    32768u
#define T_RING 49152u
#define SMEM_BYTES 65536
// fp32 i_in staging (32KB) aliases X0+X1 after MMA.

// 4 split-weight tiles [W0,W1,R0,R1], ks-major fragment order:
// frag f = (ks*16 + nb)*32 + lane ; u64 = {b0:half2, b1:half2}.
// One ks-stage of one tile = 512 u64 = 4KB contiguous.
__device__ __align__(16) u64 g_wfrag[4][4096];

static __device__ __forceinline__ u32 s2u(const void* p){
  u32 a; asm("{ .reg .u64 t; cvta.to.shared.u64 t, %1; cvt.u32.u64 %0, t; }":"=r"(a):"l"(p)); return a;
}
static __device__ __forceinline__ u32 swz16(int r, int c){   // fp16 tile, 256B rows
  return (u32)((r<<8) + ((((c>>3) ^ (r&7)) & 15)<<4) + ((c&7)<<1));
}
static __device__ __forceinline__ u32 swz32(int r, int c){   // fp32 staging, 512B rows
  return (u32)((r<<9) + ((((c>>2) ^ (r&7)) & 31)<<4) + ((c&3)<<2));
}
static __device__ __forceinline__ void sts64(u32 a, u32 lo, u32 hi){
  asm volatile("st.shared.v2.u32 [%0], {%1,%2};"::"r"(a),"r"(lo),"r"(hi));
}
static __device__ __forceinline__ void stsf2(u32 a, float x, float y){
  asm volatile("st.shared.v2.f32 [%0], {%1,%2};"::"r"(a),"f"(x),"f"(y));
}
static __device__ __forceinline__ u32 h2u(__half2 h){ return *reinterpret_cast<u32*>(&h); }

static __device__ __forceinline__ void split_store4(u32 a0, u32 a1, float4 f){
  __half h00=__float2half_rn(f.x), h01=__float2half_rn(f.y);
  __half h02=__float2half_rn(f.z), h03=__float2half_rn(f.w);
  sts64(a0, h2u(__halves2half2(h00,h01)), h2u(__halves2half2(h02,h03)));
  __half h10=__float2half_rn(f.x-__half2float(h00));
  __half h11=__float2half_rn(f.y-__half2float(h01));
  __half h12=__float2half_rn(f.z-__half2float(h02));
  __half h13=__float2half_rn(f.w-__half2float(h03));
  sts64(a1, h2u(__halves2half2(h10,h11)), h2u(__halves2half2(h12,h13)));
}
static __device__ __forceinline__ void ldsm4(u32 addr, u32* r){
  asm volatile("ldmatrix.sync.aligned.m8n8.x4.shared.b16 {%0,%1,%2,%3}, [%4];"
               : "=r"(r[0]),"=r"(r[1]),"=r"(r[2]),"=r"(r[3]) : "r"(addr));
}
static __device__ __forceinline__ void mma16816(float* c, const u32* a, u32 b0, u32 b1){
  asm volatile("mma.sync.aligned.m16n8k16.row.col.f32.f16.f16.f32 "
               "{%0,%1,%2,%3}, {%4,%5,%6,%7}, {%8,%9}, {%0,%1,%2,%3};"
               : "+f"(c[0]),"+f"(c[1]),"+f"(c[2]),"+f"(c[3])
               : "r"(a[0]),"r"(a[1]),"r"(a[2]),"r"(a[3]), "r"(b0),"r"(b1));
}
static __device__ __forceinline__ void cpasync16(u32 dst, const void* src){
  asm volatile("cp.async.cg.shared.global [%0], [%1], 16;" :: "r"(dst), "l"(src));
}

// ---- prep: split w*64 into ks-major fragment-ordered fp16 tiles (once/launch)
__global__ void prep_wfrag(const float* __restrict__ win,
                           const float* __restrict__ wrec)
{
  int idx = blockIdx.x * blockDim.x + threadIdx.x;   // 0..8191
  int mat = idx >> 12;        // 0=w_in, 1=w_rec
  int f   = idx & 4095;
  int ks   = f >> 9;          // kstep 0..7
  int nb   = (f >> 5) & 15;   // n8 block 0..15
  int lane = f & 31;
  int n  = nb*8 + (lane >> 2);
  int kb = ks*16 + (lane & 3)*2;
  const float* W = mat ? wrec : win;
  float w[4] = { W[kb*128 + n]     * WSCALE, W[(kb+1)*128 + n] * WSCALE,
                 W[(kb+8)*128 + n] * WSCALE, W[(kb+9)*128 + n] * WSCALE };
  __half p[4], r[4];
#pragma unroll
  for (int i = 0; i < 4; i++) {
    p[i] = __float2half_rn(w[i]);
    r[i] = __float2half_rn(w[i] - __half2float(p[i]));
  }
  u64 prim = ((u64)h2u(__halves2half2(p[2],p[3])) << 32) | h2u(__halves2half2(p[0],p[1]));
  u64 resi = ((u64)h2u(__halves2half2(r[2],r[3])) << 32) | h2u(__halves2half2(r[0],r[1]));
  g_wfrag[mat*2 + 0][f] = prim;
  g_wfrag[mat*2 + 1][f] = resi;
}

__global__ __launch_bounds__(TBX, 3)
void lif_hmma_kernel(const float* __restrict__ gx, const float* __restrict__ gz,
                     const float* __restrict__ gv, const float* __restrict__ gt,
                     float* __restrict__ out, int Btot, long long out_elems)
{
  extern __shared__ __align__(1024) char smem[];
  const u32 sb = s2u(smem);
  const int tid = threadIdx.x;
  const int wid = tid >> 5, lid = tid & 31;
  const u32 browg = (u32)blockIdx.x * 64;      // 64-row tile

  const int wr = wid & 1;                  // row group (32 rows)
  const int wc = wid >> 1;                 // col quarter (32 cols, 4 n8 blocks)
  const int mrow = wr << 5;

  // stage s (0..31): ks = s>>2, B tile bt = s&3 (W0,W1,R0,R1).
  // CTA-shared ring: 4 slots x 4KB; every thread copies 16B per stage.
  auto issue_stage = [&](int s){
    if (s < 32) {
      const char* src = reinterpret_cast<const char*>(g_wfrag[s & 3])
                      + (s >> 2)*4096 + tid*16;
      cpasync16(sb + T_RING + (u32)(((s & 3)*4096) + tid*16), src);
    }
    asm volatile("cp.async.commit_group;" ::: "memory");
  };

  issue_stage(0); issue_stage(1); issue_stage(2);

  // ===== producer: x split + z pack into smem (64x128) =====
  {
    const float4* X4 = reinterpret_cast<const float4*>(gx) + (size_t)browg*32;
    const float4* Z4 = reinterpret_cast<const float4*>(gz) + (size_t)browg*32;
#pragma unroll
    for (int q = 0; q < 8; q++) {
      int e = q*TBX + tid;                 // 2048 float4 = 64x128
      int r = e >> 5, c4 = (e & 31) << 2;
      u32 so = swz16(r, c4);
      split_store4(sb + T_X0 + so, sb + T_X1 + so, X4[e]);
      float4 zv = Z4[e];
      sts64(sb + T_Z + so,
            h2u(__floats2half2_rn(zv.x, zv.y)),
            h2u(__floats2half2_rn(zv.z, zv.w)));
    }
  }
  __syncthreads();      // X/Z ready

  // ===== MMA mainloop: lockstep shared ring; A fragments reused =====
  const int a_r  = (lid & 7) + ((lid >> 3) & 1) * 8;
  const int a_k8 = (lid >> 4) * 8;

  float acc[2][4][4];
#pragma unroll
  for (int mt = 0; mt < 2; mt++)
#pragma unroll
    for (int j = 0; j < 4; j++)
#pragma unroll
      for (int k = 0; k < 4; k++) acc[mt][j][k] = 0.0f;

#pragma unroll 1
  for (int ks = 0; ks < 8; ks++) {
    const int kb = ks << 4;
    const int s0 = ks << 2;
    u32 ax0[2][4], ax1[2][4], az[2][4];
    uint2 b[4];

    auto read_b = [&](int s){
      asm volatile("cp.async.wait_group 2;" ::: "memory");
      __syncthreads();                     // stage s visible; stage s-1 fully read
      const u32 rbase = sb + T_RING + (u32)(((s & 3)*4096) + wc*1024 + lid*8);
#pragma unroll
      for (int j = 0; j < 4; j++)
        asm volatile("ld.shared.v2.u32 {%0,%1}, [%2];"
                     : "=r"(b[j].x), "=r"(b[j].y) : "r"(rbase + (u32)(j*256)));
    };

    // bt=0 : W0 with x0 and x1
    read_b(s0);
#pragma unroll
    for (int mt = 0; mt < 2; mt++) {
      ldsm4(sb + T_X0 + swz16(mrow + mt*16 + a_r, kb + a_k8), ax0[mt]);
      ldsm4(sb + T_X1 + swz16(mrow + mt*16 + a_r, kb + a_k8), ax1[mt]);
    }
#pragma unroll
    for (int mt = 0; mt < 2; mt++)
#pragma unroll
      for (int j = 0; j < 4; j++) {
        mma16816(acc[mt][j], ax0[mt], b[j].x, b[j].y);
        mma16816(acc[mt][j], ax1[mt], b[j].x, b[j].y);
      }
    issue_stage(s0 + 3);

    // bt=1 : W1 with x0 (reused)
    read_b(s0 + 1);
#pragma unroll
    for (int mt = 0; mt < 2; mt++)
#pragma unroll
      for (int j = 0; j < 4; j++)
        mma16816(acc[mt][j], ax0[mt], b[j].x, b[j].y);
    issue_stage(s0 + 4);

    // bt=2 : R0 with z
    read_b(s0 + 2);
#pragma unroll
    for (int mt = 0; mt < 2; mt++)
      ldsm4(sb + T_Z + swz16(mrow + mt*16 + a_r, kb + a_k8), az[mt]);
#pragma unroll
    for (int mt = 0; mt < 2; mt++)
#pragma unroll
      for (int j = 0; j < 4; j++)
        mma16816(acc[mt][j], az[mt], b[j].x, b[j].y);
    issue_stage(s0 + 5);

    // bt=3 : R1 with z (reused)
    read_b(s0 + 3);
#pragma unroll
    for (int mt = 0; mt < 2; mt++)
#pragma unroll
      for (int j = 0; j < 4; j++)
        mma16816(acc[mt][j], az[mt], b[j].x, b[j].y);
    issue_stage(s0 + 6);
  }

  __syncthreads();   // all X0/X1 ldmatrix reads done before staging overwrites

  // ===== acc -> fp32 i_in staging (aliases X0/X1), scaled by 1/64 =====
  {
    const int rq = lid >> 2, cq = (lid & 3) << 1;
    const int ncol = wc << 5;
#pragma unroll
    for (int mt = 0; mt < 2; mt++) {
      const int r0 = mrow + mt*16 + rq;
#pragma unroll
      for (int j = 0; j < 4; j++) {
        const int c = ncol + j*8 + cq;
        stsf2(sb + swz32(r0,     c), acc[mt][j][0]*INV_WSCALE, acc[mt][j][1]*INV_WSCALE);
        stsf2(sb + swz32(r0 + 8, c), acc[mt][j][2]*INV_WSCALE, acc[mt][j][3]*INV_WSCALE);
      }
    }
  }
  __syncthreads();

  // ===== coalesced fused LIF epilogue =====
  const float L2D = -0.07400058144377693f;   // log2(0.95)
  const u32 NB = (u32)Btot * 128u;
  const bool has_t = (out_elems >= (long long)NB * 3);
#pragma unroll
  for (int q = 0; q < 8; q++) {
    int e4  = ((q << 8) + tid) << 2;         // 0..8188
    int row = e4 >> 7, col = e4 & 127;
    float4 iv;
    asm volatile("ld.shared.v4.f32 {%0,%1,%2,%3}, [%4];"
                 : "=f"(iv.x),"=f"(iv.y),"=f"(iv.z),"=f"(iv.w)
                 : "r"(sb + swz32(row, col)));
    u32 zl, zh;
    asm volatile("ld.shared.v2.u32 {%0,%1}, [%2];" : "=r"(zl),"=r"(zh)
                 : "r"(sb + T_Z + swz16(row, col)));
    __half2 zp0 = *reinterpret_cast<__half2*>(&zl);
    __half2 zp1 = *reinterpret_cast<__half2*>(&zh);
    float zf[4] = {__half2float(__low2half(zp0)), __half2float(__high2half(zp0)),
                   __half2float(__low2half(zp1)), __half2float(__high2half(zp1))};
    u32 gi = browg*128u + (u32)e4;
    float4 vv = reinterpret_cast<const float4*>(gv)[gi>>2];
    float4 tv = reinterpret_cast<const float4*>(gt)[gi>>2];
    float ia[4] = {iv.x, iv.y, iv.z, iv.w};
    float va[4] = {vv.x, vv.y, vv.z, vv.w};
    float ta[4] = {tv.x, tv.y, tv.z, tv.w};
    float nzo[4], nvo[4], nto[4];
#pragma unroll
    for (int j = 0; j < 4; j++) {
      float iin = ia[j];
      float h  = (iin != 0.0f) ? 1.0f : 0.0f;
      float nt = ta[j] + (1.0f - h);
      float nv = va[j] * (1.0f - zf[j]);
      if (!(va[j] > -1.0f)) nv -= (va[j] + 1.0f);
      nv *= exp2f(h * (nt + 1.0f) * L2D);
      nt *= (1.0f - h);
      nv += iin;
      nzo[j] = (nv > 0.4f) ? 1.0f : 0.0f;
      nvo[j] = nv; nto[j] = nt;
    }
    float4 o;
    o.x=nzo[0]; o.y=nzo[1]; o.z=nzo[2]; o.w=nzo[3];
    *reinterpret_cast<float4*>(&out[gi]) = o;
    o.x=nvo[0]; o.y=nvo[1]; o.z=nvo[2]; o.w=nvo[3];
    *reinterpret_cast<float4*>(&out[NB + gi]) = o;
    if (has_t) {
      o.x=nto[0]; o.y=nto[1]; o.z=nto[2]; o.w=nto[3];
      *reinterpret_cast<float4*>(&out[2u*NB + gi]) = o;
    }
  }
}

extern "C" void kernel_launch(void* const* d_in, const int* in_sizes, int n_in,
                              void* d_out, int out_size)
{
  const float* x     = (const float*)d_in[0];
  const float* z     = (const float*)d_in[1];
  const float* v     = (const float*)d_in[2];
  const float* t     = (const float*)d_in[3];
  const float* w_in  = (const float*)d_in[4];
  const float* w_rec = (const float*)d_in[5];

  const int B = in_sizes[0] / 128;       // 131072
  const int grid = B / 64;               // 2048 CTAs

  cudaFuncSetAttribute(lif_hmma_kernel,
                       cudaFuncAttributeMaxDynamicSharedMemorySize, SMEM_BYTES);

  prep_wfrag<<<32, 256>>>(w_in, w_rec);
  lif_hmma_kernel<<<grid, TBX, SMEM_BYTES>>>(x, z, v, t,
                                             (float*)d_out, B, (long long)out_size);
}